// round 8
// baseline (speedup 1.0000x reference)
#include <cuda_runtime.h>
#include <math.h>

#define N_NODES 50000
#define N_EDGES 800000
#define E_TOT   (N_EDGES + N_NODES)   // with self loops = 850000
#define IN_C    768
#define HID     64
#define OUT_C   8
#define BN_EPS  1e-5f
#define NEG_SLOPE 0.2f

typedef unsigned long long u64;

// ---------------- device scratch (allocation-free) ----------------
__device__ float g_h[N_NODES * HID];        // current node features
__device__ float g_xw[N_NODES * HID];       // h @ W per conv
__device__ float g_asrc[N_NODES * 8];
__device__ float g_adst[N_NODES * 8];
// CSR (built once per launch; graph shared by both convs)
__device__ int g_cnt[N_NODES];              // degree counts -> local scans
__device__ int g_indptr[N_NODES + 1];
__device__ int g_cursor[N_NODES];
__device__ int g_csr[E_TOT];                // src ids grouped by dst
__device__ int g_bsum[256];                 // block sums for scan

// ---------------- helpers ----------------
__device__ __forceinline__ float lrelu(float x) {
    return x > 0.f ? x : NEG_SLOPE * x;
}
__device__ __forceinline__ float elu1(float x) {
    return x > 0.f ? x : (expf(x) - 1.f);
}
__device__ __forceinline__ u64 pk2(float lo, float hi) {
    u64 r; asm("mov.b64 %0, {%1, %2};" : "=l"(r) : "f"(lo), "f"(hi)); return r;
}
__device__ __forceinline__ void fma2(u64& d, u64 a, u64 b) {
    asm("fma.rn.f32x2 %0, %1, %2, %0;" : "+l"(d) : "l"(a), "l"(b));
}
__device__ __forceinline__ float2 upk(u64 v) {
    float2 r; asm("mov.b64 {%0, %1}, %2;" : "=f"(r.x), "=f"(r.y) : "l"(v)); return r;
}
__device__ __forceinline__ void edge_decode(const int* __restrict__ ei, int e,
                                            int& src, int& dst) {
    if (e < N_EDGES) { src = ei[e]; dst = ei[N_EDGES + e]; }
    else             { src = dst = e - N_EDGES; }
}

// ================= CSR build =================
__global__ void k_zero_cnt()
{
    int i = blockIdx.x * blockDim.x + threadIdx.x;
    if (i < N_NODES) g_cnt[i] = 0;
}

__global__ void k_count(const int* __restrict__ ei)
{
    int e = blockIdx.x * blockDim.x + threadIdx.x;
    if (e >= E_TOT) return;
    int src, dst;
    edge_decode(ei, e, src, dst);
    atomicAdd(&g_cnt[dst], 1);
}

// per-block exclusive scan of 256 counts; writes local exclusive values back
// into g_cnt and per-block totals into g_bsum
__global__ __launch_bounds__(256) void k_scan_blk()
{
    __shared__ int sh[256];
    int t = threadIdx.x;
    int i = blockIdx.x * 256 + t;
    int c = (i < N_NODES) ? g_cnt[i] : 0;
    sh[t] = c;
    __syncthreads();
    // Hillis-Steele inclusive scan
    int v = c;
#pragma unroll
    for (int off = 1; off < 256; off <<= 1) {
        int add = (t >= off) ? sh[t - off] : 0;
        __syncthreads();
        v += add;
        sh[t] = v;
        __syncthreads();
    }
    if (i < N_NODES) g_cnt[i] = v - c;         // exclusive local
    if (t == 255) g_bsum[blockIdx.x] = v;      // block total
}

// single block: exclusive scan of block sums (<=256 entries)
__global__ __launch_bounds__(256) void k_scan_top(int nblk)
{
    __shared__ int sh[256];
    int t = threadIdx.x;
    int c = (t < nblk) ? g_bsum[t] : 0;
    sh[t] = c;
    __syncthreads();
    int v = c;
#pragma unroll
    for (int off = 1; off < 256; off <<= 1) {
        int add = (t >= off) ? sh[t - off] : 0;
        __syncthreads();
        v += add;
        sh[t] = v;
        __syncthreads();
    }
    if (t < nblk) g_bsum[t] = v - c;           // exclusive
}

__global__ void k_scan_add()
{
    int i = blockIdx.x * blockDim.x + threadIdx.x;
    if (i < N_NODES) {
        int v = g_cnt[i] + g_bsum[i >> 8];
        g_indptr[i] = v;
        g_cursor[i] = v;
    }
    if (i == 0) g_indptr[N_NODES] = E_TOT;
}

__global__ void k_scatter(const int* __restrict__ ei)
{
    int e = blockIdx.x * blockDim.x + threadIdx.x;
    if (e >= E_TOT) return;
    int src, dst;
    edge_decode(ei, e, src, dst);
    int pos = atomicAdd(&g_cursor[dst], 1);
    g_csr[pos] = src;
}

// ---------------- K1: h = elu(bn1(x @ proj_W + proj_b)) ----------------
// tile: 64 rows x 64 cols, 128 threads, 8x4 register block, FFMA2 inner loop
__global__ __launch_bounds__(128) void k_gemm_in(
    const float* __restrict__ x, const float* __restrict__ W,
    const float* __restrict__ pb,
    const float* __restrict__ bg, const float* __restrict__ bb,
    const float* __restrict__ bm, const float* __restrict__ bv)
{
    __shared__ float xs[64][65];
    __shared__ float ws[64][64];
    const int tid = threadIdx.x;
    const int r0 = blockIdx.x * 64;
    const int cg = tid & 15;      // 16 col groups of 4
    const int rg = tid >> 4;      // 8 row groups of 8
    u64 acc01[8], acc23[8];
#pragma unroll
    for (int i = 0; i < 8; i++) { acc01[i] = 0ull; acc23[i] = 0ull; }

    for (int kc = 0; kc < IN_C; kc += 64) {
#pragma unroll
        for (int i = 0; i < 8; i++) {
            int s = tid + i * 128;            // float4 slot
            int row = s >> 4, c4 = (s & 15) * 4;
            float4 val = make_float4(0.f, 0.f, 0.f, 0.f);
            int gr = r0 + row;
            if (gr < N_NODES)
                val = *(const float4*)&x[(size_t)gr * IN_C + kc + c4];
            xs[row][c4+0] = val.x; xs[row][c4+1] = val.y;
            xs[row][c4+2] = val.z; xs[row][c4+3] = val.w;
        }
#pragma unroll
        for (int i = 0; i < 8; i++) {
            int s = tid + i * 128;
            int row = s >> 4, c4 = (s & 15) * 4;
            *(float4*)&ws[row][c4] = *(const float4*)&W[(size_t)(kc + row) * HID + c4];
        }
        __syncthreads();
#pragma unroll 8
        for (int k = 0; k < 64; k++) {
            float4 w = *(float4*)&ws[k][cg * 4];
            u64 w01 = pk2(w.x, w.y);
            u64 w23 = pk2(w.z, w.w);
#pragma unroll
            for (int i = 0; i < 8; i++) {
                float xv = xs[rg * 8 + i][k];
                u64 xx = pk2(xv, xv);
                fma2(acc01[i], xx, w01);
                fma2(acc23[i], xx, w23);
            }
        }
        __syncthreads();
    }
    const int c0 = cg * 4;
    float sc[4], of[4];
#pragma unroll
    for (int j = 0; j < 4; j++) {
        int c = c0 + j;
        float s = bg[c] * rsqrtf(bv[c] + BN_EPS);
        sc[j] = s;
        of[j] = (pb[c] - bm[c]) * s + bb[c];
    }
#pragma unroll
    for (int i = 0; i < 8; i++) {
        int gr = r0 + rg * 8 + i;
        if (gr < N_NODES) {
            float2 a01 = upk(acc01[i]);
            float2 a23 = upk(acc23[i]);
            float4 o;
            o.x = elu1(a01.x * sc[0] + of[0]);
            o.y = elu1(a01.y * sc[1] + of[1]);
            o.z = elu1(a23.x * sc[2] + of[2]);
            o.w = elu1(a23.y * sc[3] + of[3]);
            *(float4*)&g_h[(size_t)gr * HID + c0] = o;
        }
    }
}

// ---------------- K2: xw = g_h @ W (64x64) ----------------
__global__ __launch_bounds__(128) void k_gemm64(const float* __restrict__ W)
{
    __shared__ float xs[64][65];
    __shared__ float ws[64][64];
    const int tid = threadIdx.x;
    const int r0 = blockIdx.x * 64;
    const int cg = tid & 15;
    const int rg = tid >> 4;
    u64 acc01[8], acc23[8];
#pragma unroll
    for (int i = 0; i < 8; i++) { acc01[i] = 0ull; acc23[i] = 0ull; }

#pragma unroll
    for (int i = 0; i < 8; i++) {
        int s = tid + i * 128;
        int row = s >> 4, c4 = (s & 15) * 4;
        float4 val = make_float4(0.f, 0.f, 0.f, 0.f);
        int gr = r0 + row;
        if (gr < N_NODES)
            val = *(const float4*)&g_h[(size_t)gr * HID + c4];
        xs[row][c4+0] = val.x; xs[row][c4+1] = val.y;
        xs[row][c4+2] = val.z; xs[row][c4+3] = val.w;
    }
#pragma unroll
    for (int i = 0; i < 8; i++) {
        int s = tid + i * 128;
        int row = s >> 4, c4 = (s & 15) * 4;
        *(float4*)&ws[row][c4] = *(const float4*)&W[(size_t)row * HID + c4];
    }
    __syncthreads();
#pragma unroll 8
    for (int k = 0; k < 64; k++) {
        float4 w = *(float4*)&ws[k][cg * 4];
        u64 w01 = pk2(w.x, w.y);
        u64 w23 = pk2(w.z, w.w);
#pragma unroll
        for (int i = 0; i < 8; i++) {
            float xv = xs[rg * 8 + i][k];
            u64 xx = pk2(xv, xv);
            fma2(acc01[i], xx, w01);
            fma2(acc23[i], xx, w23);
        }
    }
    const int c0 = cg * 4;
#pragma unroll
    for (int i = 0; i < 8; i++) {
        int gr = r0 + rg * 8 + i;
        if (gr < N_NODES) {
            float2 a01 = upk(acc01[i]);
            float2 a23 = upk(acc23[i]);
            *(float4*)&g_xw[(size_t)gr * HID + c0] =
                make_float4(a01.x, a01.y, a23.x, a23.y);
        }
    }
}

// ---------------- K3: per-node attention logits ----------------
template<int H, int C>
__global__ void k_att(const float* __restrict__ att_s,
                      const float* __restrict__ att_d)
{
    int warp = (blockIdx.x * blockDim.x + threadIdx.x) >> 5;
    int lane = threadIdx.x & 31;
    if (warp >= N_NODES) return;
    float2 xv = *(const float2*)&g_xw[warp * HID + lane * 2];
    float2 as = *(const float2*)&att_s[lane * 2];
    float2 ad = *(const float2*)&att_d[lane * 2];
    float ps = xv.x * as.x + xv.y * as.y;
    float pd = xv.x * ad.x + xv.y * ad.y;
    const int G = C / 2;   // lanes per head
#pragma unroll
    for (int off = G >> 1; off > 0; off >>= 1) {
        ps += __shfl_xor_sync(0xffffffffu, ps, off);
        pd += __shfl_xor_sync(0xffffffffu, pd, off);
    }
    if ((lane & (G - 1)) == 0) {
        int h = lane / G;
        g_asrc[warp * H + h] = ps;
        g_adst[warp * H + h] = pd;
    }
}

// ---------------- K5: gather aggregation + fused post ----------------
// warp per dst node; lane handles feature cols 2*lane, 2*lane+1
// (head = lane>>2 for H=8). Register accumulation, no atomics.
// epilogue: h = elu(bn(acc/den + bias) + h_old)
template<int H>
__global__ __launch_bounds__(256) void k_gather(
    const float* __restrict__ bias,
    const float* __restrict__ bg, const float* __restrict__ bb,
    const float* __restrict__ bm, const float* __restrict__ bv)
{
    int warp = (blockIdx.x * blockDim.x + threadIdx.x) >> 5;
    int lane = threadIdx.x & 31;
    if (warp >= N_NODES) return;
    const int dst = warp;
    const int hofs = (H == 8) ? (lane >> 2) : 0;

    float ad = g_adst[dst * H + hofs];
    int beg = g_indptr[dst];
    int end = g_indptr[dst + 1];

    float acc0 = 0.f, acc1 = 0.f, den = 0.f;
#pragma unroll 2
    for (int i = beg; i < end; i++) {
        int src = g_csr[i];
        float as = g_asrc[src * H + hofs];
        float ex = expf(lrelu(as + ad));
        float2 xv = *(const float2*)&g_xw[src * HID + lane * 2];
        acc0 += ex * xv.x;
        acc1 += ex * xv.y;
        den  += ex;
    }
    float inv = 1.f / den;

    int c0 = lane * 2;
    float s0 = bg[c0]     * rsqrtf(bv[c0]     + BN_EPS);
    float s1 = bg[c0 + 1] * rsqrtf(bv[c0 + 1] + BN_EPS);
    float2 ho = *(const float2*)&g_h[(size_t)dst * HID + c0];
    float t0 = (acc0 * inv + bias[c0]     - bm[c0])     * s0 + bb[c0]     + ho.x;
    float t1 = (acc1 * inv + bias[c0 + 1] - bm[c0 + 1]) * s1 + bb[c0 + 1] + ho.y;
    float2 o = make_float2(elu1(t0), elu1(t1));
    *(float2*)&g_h[(size_t)dst * HID + c0] = o;
}

// ---------------- K7: classifier out = h @ cls_W + cls_b ----------------
__global__ __launch_bounds__(128) void k_cls(const float* __restrict__ W,
                                             const float* __restrict__ bias,
                                             float* __restrict__ out)
{
    __shared__ float hs[128][65];
    __shared__ float ws[64][8];
    const int tid = threadIdx.x;
    const int n0 = blockIdx.x * 128;
#pragma unroll
    for (int i = 0; i < 4; i++) {
        int s = tid + i * 128;
        ws[s >> 3][s & 7] = W[s];
    }
#pragma unroll
    for (int i = 0; i < 16; i++) {
        int s = tid + i * 128;            // float4 slot
        int row = s >> 4, c4 = (s & 15) * 4;
        float4 val = make_float4(0.f, 0.f, 0.f, 0.f);
        if (n0 + row < N_NODES)
            val = *(const float4*)&g_h[(size_t)(n0 + row) * HID + c4];
        hs[row][c4+0] = val.x; hs[row][c4+1] = val.y;
        hs[row][c4+2] = val.z; hs[row][c4+3] = val.w;
    }
    __syncthreads();
    if (n0 + tid >= N_NODES) return;
    float acc[8];
#pragma unroll
    for (int jj = 0; jj < 8; jj++) acc[jj] = bias[jj];
#pragma unroll 8
    for (int k = 0; k < 64; k++) {
        float xv = hs[tid][k];
        float4 w0 = *(float4*)&ws[k][0];
        float4 w1 = *(float4*)&ws[k][4];
        acc[0] += xv * w0.x; acc[1] += xv * w0.y;
        acc[2] += xv * w0.z; acc[3] += xv * w0.w;
        acc[4] += xv * w1.x; acc[5] += xv * w1.y;
        acc[6] += xv * w1.z; acc[7] += xv * w1.w;
    }
    float* op = &out[(size_t)(n0 + tid) * 8];
    *(float4*)&op[0] = make_float4(acc[0], acc[1], acc[2], acc[3]);
    *(float4*)&op[4] = make_float4(acc[4], acc[5], acc[6], acc[7]);
}

// ---------------- launch ----------------
extern "C" void kernel_launch(void* const* d_in, const int* in_sizes, int n_in,
                              void* d_out, int out_size)
{
    const float* x        = (const float*)d_in[0];
    const int*   ei       = (const int*)  d_in[1];
    const float* proj_W   = (const float*)d_in[2];
    const float* proj_b   = (const float*)d_in[3];
    const float* bn1_g    = (const float*)d_in[4];
    const float* bn1_b    = (const float*)d_in[5];
    const float* bn1_m    = (const float*)d_in[6];
    const float* bn1_v    = (const float*)d_in[7];
    const float* bn2_g    = (const float*)d_in[8];
    const float* bn2_b    = (const float*)d_in[9];
    const float* bn2_m    = (const float*)d_in[10];
    const float* bn2_v    = (const float*)d_in[11];
    const float* bn3_g    = (const float*)d_in[12];
    const float* bn3_b    = (const float*)d_in[13];
    const float* bn3_m    = (const float*)d_in[14];
    const float* bn3_v    = (const float*)d_in[15];
    const float* W1       = (const float*)d_in[16];
    const float* att_src1 = (const float*)d_in[17];
    const float* att_dst1 = (const float*)d_in[18];
    const float* b1       = (const float*)d_in[19];
    const float* W2       = (const float*)d_in[20];
    const float* att_src2 = (const float*)d_in[21];
    const float* att_dst2 = (const float*)d_in[22];
    const float* b2       = (const float*)d_in[23];
    const float* cls_W    = (const float*)d_in[24];
    const float* cls_b    = (const float*)d_in[25];
    float* out = (float*)d_out;

    const int GEMM_BLOCKS = (N_NODES + 63) / 64;              // 782
    const int EDGE_BLOCKS = (E_TOT + 255) / 256;              // 3321
    const int NODE_BLOCKS = (N_NODES + 255) / 256;            // 196
    const int GATH_BLOCKS = (N_NODES * 32 + 255) / 256;       // 6250
    const int ATT_BLOCKS  = (N_NODES + 7) / 8;                // 6250

    // ---- CSR build (once; shared by both convs) ----
    k_zero_cnt<<<NODE_BLOCKS, 256>>>();
    k_count<<<EDGE_BLOCKS, 256>>>(ei);
    k_scan_blk<<<NODE_BLOCKS, 256>>>();
    k_scan_top<<<1, 256>>>(NODE_BLOCKS);
    k_scan_add<<<NODE_BLOCKS, 256>>>();
    k_scatter<<<EDGE_BLOCKS, 256>>>(ei);

    // projection + bn1 + elu
    k_gemm_in<<<GEMM_BLOCKS, 128>>>(x, proj_W, proj_b, bn1_g, bn1_b, bn1_m, bn1_v);

    // ---- conv1 (H=8, C=8) ----
    k_gemm64<<<GEMM_BLOCKS, 128>>>(W1);
    k_att<8, 8><<<ATT_BLOCKS, 256>>>(att_src1, att_dst1);
    k_gather<8><<<GATH_BLOCKS, 256>>>(b1, bn2_g, bn2_b, bn2_m, bn2_v);

    // ---- conv2 (H=1, C=64) ----
    k_gemm64<<<GEMM_BLOCKS, 128>>>(W2);
    k_att<1, 64><<<ATT_BLOCKS, 256>>>(att_src2, att_dst2);
    k_gather<1><<<GATH_BLOCKS, 256>>>(b2, bn3_g, bn3_b, bn3_m, bn3_v);

    // classifier
    k_cls<<<(N_NODES + 127) / 128, 128>>>(cls_W, cls_b, out);
}

// round 9
// speedup vs baseline: 1.2372x; 1.2372x over previous
#include <cuda_runtime.h>
#include <math.h>

#define N_NODES 50000
#define N_EDGES 800000
#define E_TOT   (N_EDGES + N_NODES)   // with self loops = 850000
#define IN_C    768
#define HID     64
#define OUT_C   8
#define BN_EPS  1e-5f
#define NEG_SLOPE 0.2f

typedef unsigned long long u64;

// ---------------- device scratch (allocation-free) ----------------
__device__ float g_h[N_NODES * HID];        // current node features
__device__ float g_xw[N_NODES * HID];       // h @ W per conv
__device__ float g_asrc[N_NODES * 8];
__device__ float g_adst[N_NODES * 8];
__device__ float g_denom[N_NODES * 8];
__device__ float g_agg[N_NODES * HID];      // unnormalized aggregation

// ---------------- helpers ----------------
__device__ __forceinline__ float lrelu(float x) {
    return x > 0.f ? x : NEG_SLOPE * x;
}
__device__ __forceinline__ float elu1(float x) {
    return x > 0.f ? x : (expf(x) - 1.f);
}
__device__ __forceinline__ u64 pk2(float lo, float hi) {
    u64 r; asm("mov.b64 %0, {%1, %2};" : "=l"(r) : "f"(lo), "f"(hi)); return r;
}
__device__ __forceinline__ void fma2(u64& d, u64 a, u64 b) {
    asm("fma.rn.f32x2 %0, %1, %2, %0;" : "+l"(d) : "l"(a), "l"(b));
}
__device__ __forceinline__ float2 upk(u64 v) {
    float2 r; asm("mov.b64 {%0, %1}, %2;" : "=f"(r.x), "=f"(r.y) : "l"(v)); return r;
}
__device__ __forceinline__ void atomicAddF4(float4* p, float4 v) {
#if __CUDA_ARCH__ >= 900
    atomicAdd(p, v);
#else
    atomicAdd(&p->x, v.x); atomicAdd(&p->y, v.y);
    atomicAdd(&p->z, v.z); atomicAdd(&p->w, v.w);
#endif
}
__device__ __forceinline__ void edge_decode(const int* __restrict__ ei, int e,
                                            int& src, int& dst) {
    if (e < N_EDGES) { src = ei[e]; dst = ei[N_EDGES + e]; }
    else             { src = dst = e - N_EDGES; }
}

// ---------------- K1: h = elu(bn1(x @ proj_W + proj_b)) ----------------
// tile: 64 rows x 64 cols, 128 threads, 8x4 register block, FFMA2 inner loop
__global__ __launch_bounds__(128) void k_gemm_in(
    const float* __restrict__ x, const float* __restrict__ W,
    const float* __restrict__ pb,
    const float* __restrict__ bg, const float* __restrict__ bb,
    const float* __restrict__ bm, const float* __restrict__ bv)
{
    __shared__ float xs[64][65];
    __shared__ float ws[64][64];
    const int tid = threadIdx.x;
    const int r0 = blockIdx.x * 64;
    const int cg = tid & 15;      // 16 col groups of 4
    const int rg = tid >> 4;      // 8 row groups of 8
    u64 acc01[8], acc23[8];
#pragma unroll
    for (int i = 0; i < 8; i++) { acc01[i] = 0ull; acc23[i] = 0ull; }

    for (int kc = 0; kc < IN_C; kc += 64) {
#pragma unroll
        for (int i = 0; i < 8; i++) {
            int s = tid + i * 128;            // float4 slot
            int row = s >> 4, c4 = (s & 15) * 4;
            float4 val = make_float4(0.f, 0.f, 0.f, 0.f);
            int gr = r0 + row;
            if (gr < N_NODES)
                val = *(const float4*)&x[(size_t)gr * IN_C + kc + c4];
            xs[row][c4+0] = val.x; xs[row][c4+1] = val.y;
            xs[row][c4+2] = val.z; xs[row][c4+3] = val.w;
        }
#pragma unroll
        for (int i = 0; i < 8; i++) {
            int s = tid + i * 128;
            int row = s >> 4, c4 = (s & 15) * 4;
            *(float4*)&ws[row][c4] = *(const float4*)&W[(size_t)(kc + row) * HID + c4];
        }
        __syncthreads();
#pragma unroll 8
        for (int k = 0; k < 64; k++) {
            float4 w = *(float4*)&ws[k][cg * 4];
            u64 w01 = pk2(w.x, w.y);
            u64 w23 = pk2(w.z, w.w);
#pragma unroll
            for (int i = 0; i < 8; i++) {
                float xv = xs[rg * 8 + i][k];
                u64 xx = pk2(xv, xv);
                fma2(acc01[i], xx, w01);
                fma2(acc23[i], xx, w23);
            }
        }
        __syncthreads();
    }
    const int c0 = cg * 4;
    float sc[4], of[4];
#pragma unroll
    for (int j = 0; j < 4; j++) {
        int c = c0 + j;
        float s = bg[c] * rsqrtf(bv[c] + BN_EPS);
        sc[j] = s;
        of[j] = (pb[c] - bm[c]) * s + bb[c];
    }
#pragma unroll
    for (int i = 0; i < 8; i++) {
        int gr = r0 + rg * 8 + i;
        if (gr < N_NODES) {
            float2 a01 = upk(acc01[i]);
            float2 a23 = upk(acc23[i]);
            float4 o;
            o.x = elu1(a01.x * sc[0] + of[0]);
            o.y = elu1(a01.y * sc[1] + of[1]);
            o.z = elu1(a23.x * sc[2] + of[2]);
            o.w = elu1(a23.y * sc[3] + of[3]);
            *(float4*)&g_h[(size_t)gr * HID + c0] = o;
        }
    }
}

// ---------------- K2: xw = g_h @ W (64x64) + FUSED attention logits ------
// epilogue computes a_src/a_dst per (row, head) via smem-atomic reduction,
// replacing the separate k_att kernel (saves 2 launches + 25.6MB re-reads).
template<int H>
__global__ __launch_bounds__(128) void k_gemm64(
    const float* __restrict__ W,
    const float* __restrict__ att_s, const float* __restrict__ att_d)
{
    __shared__ float xs[64][65];
    __shared__ float ws[64][64];
    __shared__ float rs[64][8];
    __shared__ float rd[64][8];
    const int tid = threadIdx.x;
    const int r0 = blockIdx.x * 64;
    const int cg = tid & 15;
    const int rg = tid >> 4;
    u64 acc01[8], acc23[8];
#pragma unroll
    for (int i = 0; i < 8; i++) { acc01[i] = 0ull; acc23[i] = 0ull; }

#pragma unroll
    for (int i = 0; i < 8; i++) {
        int s = tid + i * 128;
        int row = s >> 4, c4 = (s & 15) * 4;
        float4 val = make_float4(0.f, 0.f, 0.f, 0.f);
        int gr = r0 + row;
        if (gr < N_NODES)
            val = *(const float4*)&g_h[(size_t)gr * HID + c4];
        xs[row][c4+0] = val.x; xs[row][c4+1] = val.y;
        xs[row][c4+2] = val.z; xs[row][c4+3] = val.w;
    }
#pragma unroll
    for (int i = 0; i < 8; i++) {
        int s = tid + i * 128;
        int row = s >> 4, c4 = (s & 15) * 4;
        *(float4*)&ws[row][c4] = *(const float4*)&W[(size_t)row * HID + c4];
    }
    // zero attention reduction buffers (before the same barrier)
#pragma unroll
    for (int i = 0; i < 4; i++) {
        int s = tid + i * 128;          // 512 entries
        rs[s >> 3][s & 7] = 0.f;
        rd[s >> 3][s & 7] = 0.f;
    }
    __syncthreads();
#pragma unroll 8
    for (int k = 0; k < 64; k++) {
        float4 w = *(float4*)&ws[k][cg * 4];
        u64 w01 = pk2(w.x, w.y);
        u64 w23 = pk2(w.z, w.w);
#pragma unroll
        for (int i = 0; i < 8; i++) {
            float xv = xs[rg * 8 + i][k];
            u64 xx = pk2(xv, xv);
            fma2(acc01[i], xx, w01);
            fma2(acc23[i], xx, w23);
        }
    }
    const int c0 = cg * 4;
    // attention weights for this thread's 4 columns
    const float4 as4 = *(const float4*)&att_s[c0];
    const float4 ad4 = *(const float4*)&att_d[c0];
    const int h = (H == 8) ? (c0 >> 3) : 0;   // 4-col group lies in one head
#pragma unroll
    for (int i = 0; i < 8; i++) {
        int row = rg * 8 + i;
        int gr = r0 + row;
        float2 a01 = upk(acc01[i]);
        float2 a23 = upk(acc23[i]);
        if (gr < N_NODES) {
            *(float4*)&g_xw[(size_t)gr * HID + c0] =
                make_float4(a01.x, a01.y, a23.x, a23.y);
        }
        float ps = a01.x * as4.x + a01.y * as4.y + a23.x * as4.z + a23.y * as4.w;
        float pd = a01.x * ad4.x + a01.y * ad4.y + a23.x * ad4.z + a23.y * ad4.w;
        atomicAdd(&rs[row][h], ps);
        atomicAdd(&rd[row][h], pd);
    }
    __syncthreads();
    // write out per-(row, head) logits
    if (H == 8) {
#pragma unroll
        for (int i = 0; i < 4; i++) {
            int s = tid + i * 128;          // 512 = 64 rows x 8 heads
            int row = s >> 3, hh = s & 7;
            int gr = r0 + row;
            if (gr < N_NODES) {
                g_asrc[gr * 8 + hh] = rs[row][hh];
                g_adst[gr * 8 + hh] = rd[row][hh];
            }
        }
    } else {
        if (tid < 64) {
            int gr = r0 + tid;
            if (gr < N_NODES) {
                g_asrc[gr] = rs[tid][0];
                g_adst[gr] = rd[tid][0];
            }
        }
    }
}

// ---------------- K4: clear accumulators (float4 stores) ----------------
__global__ void k_init()
{
    int i = blockIdx.x * blockDim.x + threadIdx.x;   // float4 index
    if (i < N_NODES * (HID / 4))
        *(float4*)&g_agg[(size_t)i * 4] = make_float4(0.f, 0.f, 0.f, 0.f);
    if (i < N_NODES * 2)
        *(float4*)&g_denom[(size_t)i * 4] = make_float4(0.f, 0.f, 0.f, 0.f);
}

// ---------------- K5: FUSED edge pass ----------------
// 8 threads per edge; lane j handles head j (H=8) / features j*8..j*8+7.
// Unnormalized aggregation: agg[dst] += exp(lrelu(alpha)) * xw[src];
// denom[dst] += exp(lrelu(alpha)).   (softmax shift-invariant; logits bounded)
template<int H>
__global__ void k_edge(const int* __restrict__ ei)
{
    int t = blockIdx.x * blockDim.x + threadIdx.x;
    int j = t & 7;
    int e = t >> 3;
    if (e >= E_TOT) return;
    int src, dst;
    edge_decode(ei, e, src, dst);
    float ex;
    if (H == 8) {
        float a = g_asrc[src * 8 + j] + g_adst[dst * 8 + j];
        ex = expf(lrelu(a));
        atomicAdd(&g_denom[dst * 8 + j], ex);
    } else {
        float a = g_asrc[src] + g_adst[dst];
        ex = expf(lrelu(a));
        if (j == 0) atomicAdd(&g_denom[dst], ex);
    }
    const float4* xp = (const float4*)&g_xw[src * HID + j * 8];
    float4 a = xp[0], b = xp[1];
    a.x *= ex; a.y *= ex; a.z *= ex; a.w *= ex;
    b.x *= ex; b.y *= ex; b.z *= ex; b.w *= ex;
    atomicAddF4((float4*)&g_agg[dst * HID + j * 8], a);
    atomicAddF4((float4*)&g_agg[dst * HID + j * 8 + 4], b);
}

// ---------------- K6: h = elu(bn(agg/denom + bias) + h_old) ----------------
template<int H>
__global__ void k_post(const float* __restrict__ bias,
                       const float* __restrict__ bg, const float* __restrict__ bb,
                       const float* __restrict__ bm, const float* __restrict__ bv)
{
    int i4 = blockIdx.x * blockDim.x + threadIdx.x;
    if (i4 >= N_NODES * (HID / 4)) return;
    int node = i4 >> 4;
    int c0 = (i4 & 15) * 4;
    // head is constant across the 4 cols of this float4 (c0 % 8 in {0,4})
    float dn = (H == 8) ? g_denom[node * 8 + (c0 >> 3)] : g_denom[node];
    float inv = 1.f / dn;
    float4 a  = *(float4*)&g_agg[(size_t)i4 * 4];
    float4 ho = *(float4*)&g_h[(size_t)i4 * 4];
    float av[4] = { a.x * inv, a.y * inv, a.z * inv, a.w * inv };
    float hv[4] = { ho.x, ho.y, ho.z, ho.w };
    float ov[4];
#pragma unroll
    for (int jj = 0; jj < 4; jj++) {
        int c = c0 + jj;
        float s = bg[c] * rsqrtf(bv[c] + BN_EPS);
        float t = (av[jj] + bias[c] - bm[c]) * s + bb[c] + hv[jj];
        ov[jj] = elu1(t);
    }
    *(float4*)&g_h[(size_t)i4 * 4] = make_float4(ov[0], ov[1], ov[2], ov[3]);
}

// ---------------- K7: classifier out = h @ cls_W + cls_b ----------------
__global__ __launch_bounds__(128) void k_cls(const float* __restrict__ W,
                                             const float* __restrict__ bias,
                                             float* __restrict__ out)
{
    __shared__ float hs[128][65];
    __shared__ float ws[64][8];
    const int tid = threadIdx.x;
    const int n0 = blockIdx.x * 128;
#pragma unroll
    for (int i = 0; i < 4; i++) {
        int s = tid + i * 128;
        ws[s >> 3][s & 7] = W[s];
    }
#pragma unroll
    for (int i = 0; i < 16; i++) {
        int s = tid + i * 128;            // float4 slot
        int row = s >> 4, c4 = (s & 15) * 4;
        float4 val = make_float4(0.f, 0.f, 0.f, 0.f);
        if (n0 + row < N_NODES)
            val = *(const float4*)&g_h[(size_t)(n0 + row) * HID + c4];
        hs[row][c4+0] = val.x; hs[row][c4+1] = val.y;
        hs[row][c4+2] = val.z; hs[row][c4+3] = val.w;
    }
    __syncthreads();
    if (n0 + tid >= N_NODES) return;
    float acc[8];
#pragma unroll
    for (int jj = 0; jj < 8; jj++) acc[jj] = bias[jj];
#pragma unroll 8
    for (int k = 0; k < 64; k++) {
        float xv = hs[tid][k];
        float4 w0 = *(float4*)&ws[k][0];
        float4 w1 = *(float4*)&ws[k][4];
        acc[0] += xv * w0.x; acc[1] += xv * w0.y;
        acc[2] += xv * w0.z; acc[3] += xv * w0.w;
        acc[4] += xv * w1.x; acc[5] += xv * w1.y;
        acc[6] += xv * w1.z; acc[7] += xv * w1.w;
    }
    float* op = &out[(size_t)(n0 + tid) * 8];
    *(float4*)&op[0] = make_float4(acc[0], acc[1], acc[2], acc[3]);
    *(float4*)&op[4] = make_float4(acc[4], acc[5], acc[6], acc[7]);
}

// ---------------- launch ----------------
extern "C" void kernel_launch(void* const* d_in, const int* in_sizes, int n_in,
                              void* d_out, int out_size)
{
    const float* x        = (const float*)d_in[0];
    const int*   ei       = (const int*)  d_in[1];
    const float* proj_W   = (const float*)d_in[2];
    const float* proj_b   = (const float*)d_in[3];
    const float* bn1_g    = (const float*)d_in[4];
    const float* bn1_b    = (const float*)d_in[5];
    const float* bn1_m    = (const float*)d_in[6];
    const float* bn1_v    = (const float*)d_in[7];
    const float* bn2_g    = (const float*)d_in[8];
    const float* bn2_b    = (const float*)d_in[9];
    const float* bn2_m    = (const float*)d_in[10];
    const float* bn2_v    = (const float*)d_in[11];
    const float* bn3_g    = (const float*)d_in[12];
    const float* bn3_b    = (const float*)d_in[13];
    const float* bn3_m    = (const float*)d_in[14];
    const float* bn3_v    = (const float*)d_in[15];
    const float* W1       = (const float*)d_in[16];
    const float* att_src1 = (const float*)d_in[17];
    const float* att_dst1 = (const float*)d_in[18];
    const float* b1       = (const float*)d_in[19];
    const float* W2       = (const float*)d_in[20];
    const float* att_src2 = (const float*)d_in[21];
    const float* att_dst2 = (const float*)d_in[22];
    const float* b2       = (const float*)d_in[23];
    const float* cls_W    = (const float*)d_in[24];
    const float* cls_b    = (const float*)d_in[25];
    float* out = (float*)d_out;

    const int GEMM_BLOCKS = (N_NODES + 63) / 64;              // 782
    const int EDGE_BLOCKS = (E_TOT * 8 + 255) / 256;          // 26563
    const int INIT_BLOCKS = (N_NODES * (HID/4) + 255) / 256;  // 3125
    const int POST_BLOCKS = (N_NODES * (HID/4) + 255) / 256;  // 3125

    // projection + bn1 + elu
    k_gemm_in<<<GEMM_BLOCKS, 128>>>(x, proj_W, proj_b, bn1_g, bn1_b, bn1_m, bn1_v);

    // ---- conv1 (H=8, C=8) ----
    k_gemm64<8><<<GEMM_BLOCKS, 128>>>(W1, att_src1, att_dst1);
    k_init<<<INIT_BLOCKS, 256>>>();
    k_edge<8><<<EDGE_BLOCKS, 256>>>(ei);
    k_post<8><<<POST_BLOCKS, 256>>>(b1, bn2_g, bn2_b, bn2_m, bn2_v);

    // ---- conv2 (H=1, C=64) ----
    k_gemm64<1><<<GEMM_BLOCKS, 128>>>(W2, att_src2, att_dst2);
    k_init<<<INIT_BLOCKS, 256>>>();
    k_edge<1><<<EDGE_BLOCKS, 256>>>(ei);
    k_post<1><<<POST_BLOCKS, 256>>>(b2, bn3_g, bn3_b, bn3_m, bn3_v);

    // classifier
    k_cls<<<(N_NODES + 127) / 128, 128>>>(cls_W, cls_b, out);
}

// round 10
// speedup vs baseline: 1.2969x; 1.0483x over previous
#include <cuda_runtime.h>
#include <math.h>

#define N_NODES 50000
#define N_EDGES 800000
#define E_TOT   (N_EDGES + N_NODES)   // with self loops = 850000
#define IN_C    768
#define HID     64
#define OUT_C   8
#define BN_EPS  1e-5f
#define NEG_SLOPE 0.2f

typedef unsigned long long u64;

// ---------------- device scratch (allocation-free) ----------------
__device__ float g_h[N_NODES * HID];        // current node features
__device__ float g_xw[N_NODES * HID];       // h @ W per conv
__device__ float g_asrc[N_NODES * 8];
__device__ float g_adst[N_NODES * 8];
__device__ float g_denom[N_NODES * 8];
__device__ float g_agg[N_NODES * HID];      // unnormalized aggregation

// ---------------- helpers ----------------
__device__ __forceinline__ float lrelu(float x) {
    return x > 0.f ? x : NEG_SLOPE * x;
}
__device__ __forceinline__ float elu1(float x) {
    return x > 0.f ? x : (expf(x) - 1.f);
}
__device__ __forceinline__ u64 pk2(float lo, float hi) {
    u64 r; asm("mov.b64 %0, {%1, %2};" : "=l"(r) : "f"(lo), "f"(hi)); return r;
}
__device__ __forceinline__ void fma2(u64& d, u64 a, u64 b) {
    asm("fma.rn.f32x2 %0, %1, %2, %0;" : "+l"(d) : "l"(a), "l"(b));
}
__device__ __forceinline__ float2 upk(u64 v) {
    float2 r; asm("mov.b64 {%0, %1}, %2;" : "=f"(r.x), "=f"(r.y) : "l"(v)); return r;
}
__device__ __forceinline__ void atomicAddF4(float4* p, float4 v) {
#if __CUDA_ARCH__ >= 900
    atomicAdd(p, v);
#else
    atomicAdd(&p->x, v.x); atomicAdd(&p->y, v.y);
    atomicAdd(&p->z, v.z); atomicAdd(&p->w, v.w);
#endif
}
__device__ __forceinline__ void edge_decode(const int* __restrict__ ei, int e,
                                            int& src, int& dst) {
    if (e < N_EDGES) { src = ei[e]; dst = ei[N_EDGES + e]; }
    else             { src = dst = e - N_EDGES; }
}

// ---------------- K1: h = elu(bn1(x @ proj_W + proj_b)) ----------------
// tile: 64 rows x 64 cols, 128 threads, 8x4 register block, FFMA2 inner loop
__global__ __launch_bounds__(128) void k_gemm_in(
    const float* __restrict__ x, const float* __restrict__ W,
    const float* __restrict__ pb,
    const float* __restrict__ bg, const float* __restrict__ bb,
    const float* __restrict__ bm, const float* __restrict__ bv)
{
    __shared__ float xs[64][65];
    __shared__ float ws[64][64];
    const int tid = threadIdx.x;
    const int r0 = blockIdx.x * 64;
    const int cg = tid & 15;      // 16 col groups of 4
    const int rg = tid >> 4;      // 8 row groups of 8
    u64 acc01[8], acc23[8];
#pragma unroll
    for (int i = 0; i < 8; i++) { acc01[i] = 0ull; acc23[i] = 0ull; }

    for (int kc = 0; kc < IN_C; kc += 64) {
#pragma unroll
        for (int i = 0; i < 8; i++) {
            int s = tid + i * 128;            // float4 slot
            int row = s >> 4, c4 = (s & 15) * 4;
            float4 val = make_float4(0.f, 0.f, 0.f, 0.f);
            int gr = r0 + row;
            if (gr < N_NODES)
                val = *(const float4*)&x[(size_t)gr * IN_C + kc + c4];
            xs[row][c4+0] = val.x; xs[row][c4+1] = val.y;
            xs[row][c4+2] = val.z; xs[row][c4+3] = val.w;
        }
#pragma unroll
        for (int i = 0; i < 8; i++) {
            int s = tid + i * 128;
            int row = s >> 4, c4 = (s & 15) * 4;
            *(float4*)&ws[row][c4] = *(const float4*)&W[(size_t)(kc + row) * HID + c4];
        }
        __syncthreads();
#pragma unroll 8
        for (int k = 0; k < 64; k++) {
            float4 w = *(float4*)&ws[k][cg * 4];
            u64 w01 = pk2(w.x, w.y);
            u64 w23 = pk2(w.z, w.w);
#pragma unroll
            for (int i = 0; i < 8; i++) {
                float xv = xs[rg * 8 + i][k];
                u64 xx = pk2(xv, xv);
                fma2(acc01[i], xx, w01);
                fma2(acc23[i], xx, w23);
            }
        }
        __syncthreads();
    }
    const int c0 = cg * 4;
    float sc[4], of[4];
#pragma unroll
    for (int j = 0; j < 4; j++) {
        int c = c0 + j;
        float s = bg[c] * rsqrtf(bv[c] + BN_EPS);
        sc[j] = s;
        of[j] = (pb[c] - bm[c]) * s + bb[c];
    }
#pragma unroll
    for (int i = 0; i < 8; i++) {
        int gr = r0 + rg * 8 + i;
        if (gr < N_NODES) {
            float2 a01 = upk(acc01[i]);
            float2 a23 = upk(acc23[i]);
            float4 o;
            o.x = elu1(a01.x * sc[0] + of[0]);
            o.y = elu1(a01.y * sc[1] + of[1]);
            o.z = elu1(a23.x * sc[2] + of[2]);
            o.w = elu1(a23.y * sc[3] + of[3]);
            *(float4*)&g_h[(size_t)gr * HID + c0] = o;
        }
    }
}

// ---------------- K2: xw = g_h @ W (64x64) ----------------
__global__ __launch_bounds__(128) void k_gemm64(const float* __restrict__ W)
{
    __shared__ float xs[64][65];
    __shared__ float ws[64][64];
    const int tid = threadIdx.x;
    const int r0 = blockIdx.x * 64;
    const int cg = tid & 15;
    const int rg = tid >> 4;
    u64 acc01[8], acc23[8];
#pragma unroll
    for (int i = 0; i < 8; i++) { acc01[i] = 0ull; acc23[i] = 0ull; }

#pragma unroll
    for (int i = 0; i < 8; i++) {
        int s = tid + i * 128;
        int row = s >> 4, c4 = (s & 15) * 4;
        float4 val = make_float4(0.f, 0.f, 0.f, 0.f);
        int gr = r0 + row;
        if (gr < N_NODES)
            val = *(const float4*)&g_h[(size_t)gr * HID + c4];
        xs[row][c4+0] = val.x; xs[row][c4+1] = val.y;
        xs[row][c4+2] = val.z; xs[row][c4+3] = val.w;
    }
#pragma unroll
    for (int i = 0; i < 8; i++) {
        int s = tid + i * 128;
        int row = s >> 4, c4 = (s & 15) * 4;
        *(float4*)&ws[row][c4] = *(const float4*)&W[(size_t)row * HID + c4];
    }
    __syncthreads();
#pragma unroll 8
    for (int k = 0; k < 64; k++) {
        float4 w = *(float4*)&ws[k][cg * 4];
        u64 w01 = pk2(w.x, w.y);
        u64 w23 = pk2(w.z, w.w);
#pragma unroll
        for (int i = 0; i < 8; i++) {
            float xv = xs[rg * 8 + i][k];
            u64 xx = pk2(xv, xv);
            fma2(acc01[i], xx, w01);
            fma2(acc23[i], xx, w23);
        }
    }
    const int c0 = cg * 4;
#pragma unroll
    for (int i = 0; i < 8; i++) {
        int gr = r0 + rg * 8 + i;
        if (gr < N_NODES) {
            float2 a01 = upk(acc01[i]);
            float2 a23 = upk(acc23[i]);
            *(float4*)&g_xw[(size_t)gr * HID + c0] =
                make_float4(a01.x, a01.y, a23.x, a23.y);
        }
    }
}

// ---------------- K3: per-node attention logits + accumulator zeroing ----
// warp per node. Also zeroes g_agg row + g_denom entries for that node,
// replacing the separate k_init kernel (pure coalesced stores, no sync).
template<int H, int C>
__global__ void k_att(const float* __restrict__ att_s,
                      const float* __restrict__ att_d)
{
    int warp = (blockIdx.x * blockDim.x + threadIdx.x) >> 5;
    int lane = threadIdx.x & 31;
    if (warp >= N_NODES) return;

    // zero accumulators for this node (consumed by k_edge next)
    *(float2*)&g_agg[(size_t)warp * HID + lane * 2] = make_float2(0.f, 0.f);
    if (H == 8) {
        if (lane < 8) g_denom[warp * 8 + lane] = 0.f;
    } else {
        if (lane == 0) g_denom[warp] = 0.f;
    }

    float2 xv = *(const float2*)&g_xw[warp * HID + lane * 2];
    float2 as = *(const float2*)&att_s[lane * 2];
    float2 ad = *(const float2*)&att_d[lane * 2];
    float ps = xv.x * as.x + xv.y * as.y;
    float pd = xv.x * ad.x + xv.y * ad.y;
    const int G = C / 2;   // lanes per head
#pragma unroll
    for (int off = G >> 1; off > 0; off >>= 1) {
        ps += __shfl_xor_sync(0xffffffffu, ps, off);
        pd += __shfl_xor_sync(0xffffffffu, pd, off);
    }
    if ((lane & (G - 1)) == 0) {
        int h = lane / G;
        g_asrc[warp * H + h] = ps;
        g_adst[warp * H + h] = pd;
    }
}

// ---------------- K5: FUSED edge pass ----------------
// 8 threads per edge; lane j handles head j (H=8) / features j*8..j*8+7.
// Unnormalized aggregation: agg[dst] += exp(lrelu(alpha)) * xw[src];
// denom[dst] += exp(lrelu(alpha)).   (softmax shift-invariant; logits bounded)
template<int H>
__global__ void k_edge(const int* __restrict__ ei)
{
    int t = blockIdx.x * blockDim.x + threadIdx.x;
    int j = t & 7;
    int e = t >> 3;
    if (e >= E_TOT) return;
    int src, dst;
    edge_decode(ei, e, src, dst);
    float ex;
    if (H == 8) {
        float a = g_asrc[src * 8 + j] + g_adst[dst * 8 + j];
        ex = expf(lrelu(a));
        atomicAdd(&g_denom[dst * 8 + j], ex);
    } else {
        float a = g_asrc[src] + g_adst[dst];
        ex = expf(lrelu(a));
        if (j == 0) atomicAdd(&g_denom[dst], ex);
    }
    const float4* xp = (const float4*)&g_xw[src * HID + j * 8];
    float4 a = xp[0], b = xp[1];
    a.x *= ex; a.y *= ex; a.z *= ex; a.w *= ex;
    b.x *= ex; b.y *= ex; b.z *= ex; b.w *= ex;
    atomicAddF4((float4*)&g_agg[dst * HID + j * 8], a);
    atomicAddF4((float4*)&g_agg[dst * HID + j * 8 + 4], b);
}

// ---------------- K6: h = elu(bn(agg/denom + bias) + h_old) ----------------
template<int H>
__global__ void k_post(const float* __restrict__ bias,
                       const float* __restrict__ bg, const float* __restrict__ bb,
                       const float* __restrict__ bm, const float* __restrict__ bv)
{
    int i4 = blockIdx.x * blockDim.x + threadIdx.x;
    if (i4 >= N_NODES * (HID / 4)) return;
    int node = i4 >> 4;
    int c0 = (i4 & 15) * 4;
    // head is constant across the 4 cols of this float4 (c0 % 8 in {0,4})
    float dn = (H == 8) ? g_denom[node * 8 + (c0 >> 3)] : g_denom[node];
    float inv = 1.f / dn;
    float4 a  = *(float4*)&g_agg[(size_t)i4 * 4];
    float4 ho = *(float4*)&g_h[(size_t)i4 * 4];
    float av[4] = { a.x * inv, a.y * inv, a.z * inv, a.w * inv };
    float hv[4] = { ho.x, ho.y, ho.z, ho.w };
    float ov[4];
#pragma unroll
    for (int jj = 0; jj < 4; jj++) {
        int c = c0 + jj;
        float s = bg[c] * rsqrtf(bv[c] + BN_EPS);
        float t = (av[jj] + bias[c] - bm[c]) * s + bb[c] + hv[jj];
        ov[jj] = elu1(t);
    }
    *(float4*)&g_h[(size_t)i4 * 4] = make_float4(ov[0], ov[1], ov[2], ov[3]);
}

// ---------------- K7: classifier out = h @ cls_W + cls_b ----------------
__global__ __launch_bounds__(128) void k_cls(const float* __restrict__ W,
                                             const float* __restrict__ bias,
                                             float* __restrict__ out)
{
    __shared__ float hs[128][65];
    __shared__ float ws[64][8];
    const int tid = threadIdx.x;
    const int n0 = blockIdx.x * 128;
#pragma unroll
    for (int i = 0; i < 4; i++) {
        int s = tid + i * 128;
        ws[s >> 3][s & 7] = W[s];
    }
#pragma unroll
    for (int i = 0; i < 16; i++) {
        int s = tid + i * 128;            // float4 slot
        int row = s >> 4, c4 = (s & 15) * 4;
        float4 val = make_float4(0.f, 0.f, 0.f, 0.f);
        if (n0 + row < N_NODES)
            val = *(const float4*)&g_h[(size_t)(n0 + row) * HID + c4];
        hs[row][c4+0] = val.x; hs[row][c4+1] = val.y;
        hs[row][c4+2] = val.z; hs[row][c4+3] = val.w;
    }
    __syncthreads();
    if (n0 + tid >= N_NODES) return;
    float acc[8];
#pragma unroll
    for (int jj = 0; jj < 8; jj++) acc[jj] = bias[jj];
#pragma unroll 8
    for (int k = 0; k < 64; k++) {
        float xv = hs[tid][k];
        float4 w0 = *(float4*)&ws[k][0];
        float4 w1 = *(float4*)&ws[k][4];
        acc[0] += xv * w0.x; acc[1] += xv * w0.y;
        acc[2] += xv * w0.z; acc[3] += xv * w0.w;
        acc[4] += xv * w1.x; acc[5] += xv * w1.y;
        acc[6] += xv * w1.z; acc[7] += xv * w1.w;
    }
    float* op = &out[(size_t)(n0 + tid) * 8];
    *(float4*)&op[0] = make_float4(acc[0], acc[1], acc[2], acc[3]);
    *(float4*)&op[4] = make_float4(acc[4], acc[5], acc[6], acc[7]);
}

// ---------------- launch ----------------
extern "C" void kernel_launch(void* const* d_in, const int* in_sizes, int n_in,
                              void* d_out, int out_size)
{
    const float* x        = (const float*)d_in[0];
    const int*   ei       = (const int*)  d_in[1];
    const float* proj_W   = (const float*)d_in[2];
    const float* proj_b   = (const float*)d_in[3];
    const float* bn1_g    = (const float*)d_in[4];
    const float* bn1_b    = (const float*)d_in[5];
    const float* bn1_m    = (const float*)d_in[6];
    const float* bn1_v    = (const float*)d_in[7];
    const float* bn2_g    = (const float*)d_in[8];
    const float* bn2_b    = (const float*)d_in[9];
    const float* bn2_m    = (const float*)d_in[10];
    const float* bn2_v    = (const float*)d_in[11];
    const float* bn3_g    = (const float*)d_in[12];
    const float* bn3_b    = (const float*)d_in[13];
    const float* bn3_m    = (const float*)d_in[14];
    const float* bn3_v    = (const float*)d_in[15];
    const float* W1       = (const float*)d_in[16];
    const float* att_src1 = (const float*)d_in[17];
    const float* att_dst1 = (const float*)d_in[18];
    const float* b1       = (const float*)d_in[19];
    const float* W2       = (const float*)d_in[20];
    const float* att_src2 = (const float*)d_in[21];
    const float* att_dst2 = (const float*)d_in[22];
    const float* b2       = (const float*)d_in[23];
    const float* cls_W    = (const float*)d_in[24];
    const float* cls_b    = (const float*)d_in[25];
    float* out = (float*)d_out;

    const int GEMM_BLOCKS = (N_NODES + 63) / 64;              // 782
    const int EDGE_BLOCKS = (E_TOT * 8 + 255) / 256;          // 26563
    const int POST_BLOCKS = (N_NODES * (HID/4) + 255) / 256;  // 3125
    const int ATT_BLOCKS  = (N_NODES + 7) / 8;                // 6250

    // projection + bn1 + elu
    k_gemm_in<<<GEMM_BLOCKS, 128>>>(x, proj_W, proj_b, bn1_g, bn1_b, bn1_m, bn1_v);

    // ---- conv1 (H=8, C=8) ----
    k_gemm64<<<GEMM_BLOCKS, 128>>>(W1);
    k_att<8, 8><<<ATT_BLOCKS, 256>>>(att_src1, att_dst1);   // also zeroes agg/denom
    k_edge<8><<<EDGE_BLOCKS, 256>>>(ei);
    k_post<8><<<POST_BLOCKS, 256>>>(b1, bn2_g, bn2_b, bn2_m, bn2_v);

    // ---- conv2 (H=1, C=64) ----
    k_gemm64<<<GEMM_BLOCKS, 128>>>(W2);
    k_att<1, 64><<<ATT_BLOCKS, 256>>>(att_src2, att_dst2);  // also zeroes agg/denom
    k_edge<1><<<EDGE_BLOCKS, 256>>>(ei);
    k_post<1><<<POST_BLOCKS, 256>>>(b2, bn3_g, bn3_b, bn3_m, bn3_v);

    // classifier
    k_cls<<<(N_NODES + 127) / 128, 128>>>(cls_W, cls_b, out);
}